// round 1
// baseline (speedup 1.0000x reference)
#include <cuda_runtime.h>
#include <cuda_bf16.h>

// Problem constants (shapes fixed by the dataset)
#define NV   50000
#define NE   25000
#define DDIM 512
#define D4   128    // DDIM / 4

// Scratch: __device__ globals (allocation-free rule)
__device__ float g_Xp[(size_t)NV * DDIM];   // projected features  [N, D]
__device__ float g_Xe[(size_t)NE * DDIM];   // edge accumulators   [E, D]

// ---------------------------------------------------------------------------
// Zero fill
// ---------------------------------------------------------------------------
__global__ void zero_kernel(float4* __restrict__ p, int n4) {
    int i = blockIdx.x * blockDim.x + threadIdx.x;
    if (i < n4) p[i] = make_float4(0.f, 0.f, 0.f, 0.f);
}

// ---------------------------------------------------------------------------
// SGEMM: C[M, 512] = A[M, 512] * B[512, 512]^T      (A = X, B = W [out,in])
// 128x128x8 tiles, 256 threads, 8x8 per thread, fp32 FMA.
// ---------------------------------------------------------------------------
__global__ __launch_bounds__(256, 2)
void sgemm_tn_kernel(const float* __restrict__ A, const float* __restrict__ B,
                     float* __restrict__ C, int M) {
    const int K = DDIM;
    const int NC = DDIM;

    __shared__ float As[8][128];
    __shared__ float Bs[8][128];

    int tid = threadIdx.x;
    int bm = blockIdx.y * 128;
    int bn = blockIdx.x * 128;
    int tx = tid & 15;       // 0..15 -> n
    int ty = tid >> 4;       // 0..15 -> m
    int lrow = tid >> 1;     // 0..127
    int lcol = (tid & 1) * 4;

    const float* Aptr = A + (size_t)(bm + lrow) * K + lcol;
    const float* Bptr = B + (size_t)(bn + lrow) * K + lcol;
    bool av = (bm + lrow) < M;

    float acc[8][8];
#pragma unroll
    for (int i = 0; i < 8; i++)
#pragma unroll
        for (int j = 0; j < 8; j++) acc[i][j] = 0.f;

    float4 a4 = av ? *(const float4*)Aptr : make_float4(0.f, 0.f, 0.f, 0.f);
    float4 b4 = *(const float4*)Bptr;

    for (int k0 = 0; k0 < K; k0 += 8) {
        As[lcol + 0][lrow] = a4.x;
        As[lcol + 1][lrow] = a4.y;
        As[lcol + 2][lrow] = a4.z;
        As[lcol + 3][lrow] = a4.w;
        Bs[lcol + 0][lrow] = b4.x;
        Bs[lcol + 1][lrow] = b4.y;
        Bs[lcol + 2][lrow] = b4.z;
        Bs[lcol + 3][lrow] = b4.w;
        __syncthreads();

        if (k0 + 8 < K) {
            a4 = av ? *(const float4*)(Aptr + k0 + 8) : make_float4(0.f, 0.f, 0.f, 0.f);
            b4 = *(const float4*)(Bptr + k0 + 8);
        }

#pragma unroll
        for (int k = 0; k < 8; k++) {
            float a[8], b[8];
#pragma unroll
            for (int i = 0; i < 8; i++) a[i] = As[k][ty * 8 + i];
#pragma unroll
            for (int j = 0; j < 8; j++) b[j] = Bs[k][tx * 8 + j];
#pragma unroll
            for (int i = 0; i < 8; i++)
#pragma unroll
                for (int j = 0; j < 8; j++) acc[i][j] += a[i] * b[j];
        }
        __syncthreads();
    }

#pragma unroll
    for (int i = 0; i < 8; i++) {
        int row = bm + ty * 8 + i;
        if (row < M) {
            float4* cp = (float4*)(C + (size_t)row * NC + bn + tx * 8);
            cp[0] = make_float4(acc[i][0], acc[i][1], acc[i][2], acc[i][3]);
            cp[1] = make_float4(acc[i][4], acc[i][5], acc[i][6], acc[i][7]);
        }
    }
}

// ---------------------------------------------------------------------------
// Stage 1: Xe_raw[e] += Xp[v]  for each incidence pair (v, e).
// One thread per float4; vectorized global reduction (red.global.add.v4.f32).
// ---------------------------------------------------------------------------
__global__ void stage1_kernel(const int* __restrict__ vidx,
                              const int* __restrict__ eidx, int nnz) {
    int gid = blockIdx.x * blockDim.x + threadIdx.x;
    int pair = gid >> 7;
    if (pair >= nnz) return;
    int j = gid & 127;

    int v = __ldg(vidx + pair);
    int e = __ldg(eidx + pair);

    float4 val = ((const float4*)g_Xp)[(size_t)v * D4 + j];
    float4* dst = ((float4*)g_Xe) + (size_t)e * D4 + j;
    asm volatile("red.global.add.v4.f32 [%0], {%1,%2,%3,%4};"
                 :: "l"(dst), "f"(val.x), "f"(val.y), "f"(val.z), "f"(val.w)
                 : "memory");
}

// ---------------------------------------------------------------------------
// Stage 2: Xv[v] += degV[v] * degE[e] * Wdiag[e] * Xe_raw[e]  for each pair.
// Scales folded into the scatter so no separate normalize passes are needed.
// ---------------------------------------------------------------------------
__global__ void stage2_kernel(const int* __restrict__ vidx,
                              const int* __restrict__ eidx,
                              const float* __restrict__ degE,
                              const float* __restrict__ degV,
                              const float* __restrict__ Wdiag,
                              float4* __restrict__ out, int nnz) {
    int gid = blockIdx.x * blockDim.x + threadIdx.x;
    int pair = gid >> 7;
    if (pair >= nnz) return;
    int j = gid & 127;

    int v = __ldg(vidx + pair);
    int e = __ldg(eidx + pair);
    float coef = __ldg(degE + e) * __ldg(Wdiag + e) * __ldg(degV + v);

    float4 val = ((const float4*)g_Xe)[(size_t)e * D4 + j];
    val.x *= coef; val.y *= coef; val.z *= coef; val.w *= coef;

    float4* dst = out + (size_t)v * D4 + j;
    asm volatile("red.global.add.v4.f32 [%0], {%1,%2,%3,%4};"
                 :: "l"(dst), "f"(val.x), "f"(val.y), "f"(val.z), "f"(val.w)
                 : "memory");
}

// ---------------------------------------------------------------------------
// Launch
// ---------------------------------------------------------------------------
extern "C" void kernel_launch(void* const* d_in, const int* in_sizes, int n_in,
                              void* d_out, int out_size) {
    const float* X     = (const float*)d_in[0];   // [N, D]
    const float* W     = (const float*)d_in[1];   // [D_OUT, D_IN]
    const float* degE  = (const float*)d_in[2];   // [E]
    const float* degV  = (const float*)d_in[3];   // [N]
    const float* Wdiag = (const float*)d_in[4];   // [E]
    const int*   vidx  = (const int*)d_in[5];     // [NNZ]
    const int*   eidx  = (const int*)d_in[6];     // [NNZ]
    int nnz = in_sizes[5];
    int M   = in_sizes[3];                        // N vertices

    float* Xp;
    float* Xe;
    cudaGetSymbolAddress((void**)&Xp, g_Xp);
    cudaGetSymbolAddress((void**)&Xe, g_Xe);

    // Zero edge accumulators and output (output is poisoned by the harness).
    {
        int n4 = NE * D4;
        zero_kernel<<<(n4 + 255) / 256, 256>>>((float4*)Xe, n4);
    }
    {
        int n4 = out_size / 4;
        zero_kernel<<<(n4 + 255) / 256, 256>>>((float4*)d_out, n4);
    }

    // Dense projection Xp = X @ W^T
    {
        dim3 grid(DDIM / 128, (M + 127) / 128);
        sgemm_tn_kernel<<<grid, 256>>>(X, W, Xp, M);
    }

    // Stage 1: vertex -> hyperedge accumulate
    {
        long total = (long)nnz * D4;
        int blocks = (int)((total + 255) / 256);
        stage1_kernel<<<blocks, 256>>>(vidx, eidx, nnz);
    }

    // Stage 2: hyperedge -> vertex with folded normalization
    {
        long total = (long)nnz * D4;
        int blocks = (int)((total + 255) / 256);
        stage2_kernel<<<blocks, 256>>>(vidx, eidx, degE, degV, Wdiag,
                                       (float4*)d_out, nnz);
    }
}

// round 7
// speedup vs baseline: 1.3789x; 1.3789x over previous
#include <cuda_runtime.h>
#include <cuda_bf16.h>
#include <cstdint>

// Problem constants (fixed by dataset)
#define NV    50000
#define NE    25000
#define DDIM  512
#define D4    128             // DDIM/4

// ---------------------------------------------------------------------------
// Scratch (__device__ globals: allocation-free rule)
// ---------------------------------------------------------------------------
__device__ float g_Xe [(size_t)NE * DDIM];   // raw edge accumulators  [E, D]
__device__ float g_Xep[(size_t)NE * DDIM];   // projected+scaled edges [E, D]

// ---------------------------------------------------------------------------
// Zero fill
// ---------------------------------------------------------------------------
__global__ void zero_kernel(float4* __restrict__ p, int n4) {
    int i = blockIdx.x * blockDim.x + threadIdx.x;
    if (i < n4) p[i] = make_float4(0.f, 0.f, 0.f, 0.f);
}

// ---------------------------------------------------------------------------
// Stage 1: Xe_raw[e] += X[v]   (vertex -> hyperedge, fp32 vector reductions)
// ---------------------------------------------------------------------------
__global__ void stage1_kernel(const float4* __restrict__ X,
                              const int* __restrict__ vidx,
                              const int* __restrict__ eidx, int nnz) {
    int gid = blockIdx.x * blockDim.x + threadIdx.x;
    int pair = gid >> 7;
    if (pair >= nnz) return;
    int j = gid & 127;
    int v = __ldg(vidx + pair);
    int e = __ldg(eidx + pair);
    float4 val = X[(size_t)v * D4 + j];
    float4* dst = ((float4*)g_Xe) + (size_t)e * D4 + j;
    asm volatile("red.global.add.v4.f32 [%0], {%1,%2,%3,%4};"
                 :: "l"(dst), "f"(val.x), "f"(val.y), "f"(val.z), "f"(val.w) : "memory");
}

// ---------------------------------------------------------------------------
// SGEMM: C[M, 512] = rowscale[m] * (A[M, 512] * B[512, 512]^T)
//        rowscale[m] = degE[m] * Wdiag[m]
// 128x128x8 tiles, 256 threads, 8x8 per thread, fp32 FMA. (R1-proven core.)
// ---------------------------------------------------------------------------
__global__ __launch_bounds__(256, 2)
void sgemm_tn_kernel(const float* __restrict__ A, const float* __restrict__ B,
                     const float* __restrict__ degE,
                     const float* __restrict__ Wdiag,
                     float* __restrict__ C, int M) {
    const int K = DDIM;
    const int NC = DDIM;

    __shared__ float As[8][128];
    __shared__ float Bs[8][128];

    int tid = threadIdx.x;
    int bm = blockIdx.y * 128;
    int bn = blockIdx.x * 128;
    int tx = tid & 15;       // 0..15 -> n
    int ty = tid >> 4;       // 0..15 -> m
    int lrow = tid >> 1;     // 0..127
    int lcol = (tid & 1) * 4;

    const float* Aptr = A + (size_t)(bm + lrow) * K + lcol;
    const float* Bptr = B + (size_t)(bn + lrow) * K + lcol;
    bool av = (bm + lrow) < M;

    float acc[8][8];
#pragma unroll
    for (int i = 0; i < 8; i++)
#pragma unroll
        for (int j = 0; j < 8; j++) acc[i][j] = 0.f;

    float4 a4 = av ? *(const float4*)Aptr : make_float4(0.f, 0.f, 0.f, 0.f);
    float4 b4 = *(const float4*)Bptr;

    for (int k0 = 0; k0 < K; k0 += 8) {
        As[lcol + 0][lrow] = a4.x;
        As[lcol + 1][lrow] = a4.y;
        As[lcol + 2][lrow] = a4.z;
        As[lcol + 3][lrow] = a4.w;
        Bs[lcol + 0][lrow] = b4.x;
        Bs[lcol + 1][lrow] = b4.y;
        Bs[lcol + 2][lrow] = b4.z;
        Bs[lcol + 3][lrow] = b4.w;
        __syncthreads();

        if (k0 + 8 < K) {
            a4 = av ? *(const float4*)(Aptr + k0 + 8) : make_float4(0.f, 0.f, 0.f, 0.f);
            b4 = *(const float4*)(Bptr + k0 + 8);
        }

#pragma unroll
        for (int k = 0; k < 8; k++) {
            float a[8], b[8];
#pragma unroll
            for (int i = 0; i < 8; i++) a[i] = As[k][ty * 8 + i];
#pragma unroll
            for (int j = 0; j < 8; j++) b[j] = Bs[k][tx * 8 + j];
#pragma unroll
            for (int i = 0; i < 8; i++)
#pragma unroll
                for (int j = 0; j < 8; j++) acc[i][j] += a[i] * b[j];
        }
        __syncthreads();
    }

#pragma unroll
    for (int i = 0; i < 8; i++) {
        int row = bm + ty * 8 + i;
        if (row < M) {
            float s = degE[row] * Wdiag[row];
            float4* cp = (float4*)(C + (size_t)row * NC + bn + tx * 8);
            cp[0] = make_float4(acc[i][0] * s, acc[i][1] * s, acc[i][2] * s, acc[i][3] * s);
            cp[1] = make_float4(acc[i][4] * s, acc[i][5] * s, acc[i][6] * s, acc[i][7] * s);
        }
    }
}

// ---------------------------------------------------------------------------
// Stage 2: out[v] += degV[v] * Xep[e]   (edge -> vertex, fp32 reductions)
// ---------------------------------------------------------------------------
__global__ void stage2_kernel(const int* __restrict__ vidx,
                              const int* __restrict__ eidx,
                              const float* __restrict__ degV,
                              float4* __restrict__ out, int nnz) {
    int gid = blockIdx.x * blockDim.x + threadIdx.x;
    int pair = gid >> 7;
    if (pair >= nnz) return;
    int j = gid & 127;
    int v = __ldg(vidx + pair);
    int e = __ldg(eidx + pair);
    float coef = __ldg(degV + v);
    float4 val = ((const float4*)g_Xep)[(size_t)e * D4 + j];
    val.x *= coef; val.y *= coef; val.z *= coef; val.w *= coef;
    float4* dst = out + (size_t)v * D4 + j;
    asm volatile("red.global.add.v4.f32 [%0], {%1,%2,%3,%4};"
                 :: "l"(dst), "f"(val.x), "f"(val.y), "f"(val.z), "f"(val.w) : "memory");
}

// ---------------------------------------------------------------------------
// Launch
// ---------------------------------------------------------------------------
extern "C" void kernel_launch(void* const* d_in, const int* in_sizes, int n_in,
                              void* d_out, int out_size) {
    const float* X     = (const float*)d_in[0];
    const float* W     = (const float*)d_in[1];
    const float* degE  = (const float*)d_in[2];
    const float* degV  = (const float*)d_in[3];
    const float* Wdiag = (const float*)d_in[4];
    const int*   vidx  = (const int*)d_in[5];
    const int*   eidx  = (const int*)d_in[6];
    int nnz = in_sizes[5];
    int E   = in_sizes[2];

    float *Xe, *Xep;
    cudaGetSymbolAddress((void**)&Xe,  g_Xe);
    cudaGetSymbolAddress((void**)&Xep, g_Xep);

    // Zero edge accumulators and output (output is poisoned by the harness).
    {
        int n4 = NE * D4;
        zero_kernel<<<(n4 + 255) / 256, 256>>>((float4*)Xe, n4);
    }
    {
        int n4 = out_size / 4;
        zero_kernel<<<(n4 + 255) / 256, 256>>>((float4*)d_out, n4);
    }

    // Stage 1: aggregate raw X into edge accumulators
    {
        long total = (long)nnz * D4;
        int blocks = (int)((total + 255) / 256);
        stage1_kernel<<<blocks, 256>>>((const float4*)X, vidx, eidx, nnz);
    }

    // Edge-side projection: Xep = (degE*Wdiag) ⊙ (Xe @ W^T)   [25000 x 512]
    {
        dim3 grid(DDIM / 128, (E + 127) / 128);
        sgemm_tn_kernel<<<grid, 256>>>(Xe, W, degE, Wdiag, Xep, E);
    }

    // Stage 2: edge -> vertex with degV
    {
        long total = (long)nnz * D4;
        int blocks = (int)((total + 255) / 256);
        stage2_kernel<<<blocks, 256>>>(vidx, eidx, degV, (float4*)d_out, nnz);
    }
}

// round 8
// speedup vs baseline: 1.7102x; 1.2403x over previous
#include <cuda_runtime.h>
#include <cuda_bf16.h>
#include <cstdint>

// Problem constants (fixed by dataset)
#define NV     50000
#define NE     25000
#define NE_PAD 25088          // 196 * 128
#define DDIM   512
#define D4     128            // DDIM/4
#define KTOT   1536           // 3 * DDIM (K-concat of bf16 splits)
#define KC     32             // K-chunk
#define NCH    (KTOT / KC)    // 48
#define ASTR   40             // smem row stride in bf16 (conflict-free ldmatrix)

// ---------------------------------------------------------------------------
// Scratch (__device__ globals; pad rows of g_A stay zero from static init,
// nothing ever writes them -> deterministic)
// ---------------------------------------------------------------------------
__device__ float          g_Xe [(size_t)NE * DDIM];        // raw edge accum [E, D]
__device__ float          g_Xep[(size_t)NE * DDIM];        // projected edges [E, D]
__device__ __nv_bfloat16  g_A  [(size_t)NE_PAD * KTOT];    // [hi(Xe) | lo(Xe) | hi(Xe)]
__device__ __nv_bfloat16  g_B  [(size_t)DDIM * KTOT];      // [hi(W)  | hi(W)  | lo(W) ]

// ---------------------------------------------------------------------------
// Zero fill
// ---------------------------------------------------------------------------
__global__ void zero_kernel(float4* __restrict__ p, int n4) {
    int i = blockIdx.x * blockDim.x + threadIdx.x;
    if (i < n4) p[i] = make_float4(0.f, 0.f, 0.f, 0.f);
}

// ---------------------------------------------------------------------------
// Stage 1: Xe_raw[e] += X[v]   (vertex -> hyperedge, fp32 vector reductions)
// ---------------------------------------------------------------------------
__global__ void stage1_kernel(const float4* __restrict__ X,
                              const int* __restrict__ vidx,
                              const int* __restrict__ eidx, int nnz) {
    int gid = blockIdx.x * blockDim.x + threadIdx.x;
    int pair = gid >> 7;
    if (pair >= nnz) return;
    int j = gid & 127;
    int v = __ldg(vidx + pair);
    int e = __ldg(eidx + pair);
    float4 val = X[(size_t)v * D4 + j];
    float4* dst = ((float4*)g_Xe) + (size_t)e * D4 + j;
    asm volatile("red.global.add.v4.f32 [%0], {%1,%2,%3,%4};"
                 :: "l"(dst), "f"(val.x), "f"(val.y), "f"(val.z), "f"(val.w) : "memory");
}

// ---------------------------------------------------------------------------
// Split kernels: fp32 -> bf16 hi/lo, written as 3 K-segments per row.
// Each thread handles one float4 (4 values -> one uint2 = 4 bf16 per segment).
// ---------------------------------------------------------------------------
__device__ __forceinline__ void split4(float4 v, uint32_t& h01, uint32_t& h23,
                                       uint32_t& l01, uint32_t& l23) {
    __nv_bfloat16 hx = __float2bfloat16(v.x), hy = __float2bfloat16(v.y);
    __nv_bfloat16 hz = __float2bfloat16(v.z), hw = __float2bfloat16(v.w);
    __nv_bfloat16 lx = __float2bfloat16(v.x - __bfloat162float(hx));
    __nv_bfloat16 ly = __float2bfloat16(v.y - __bfloat162float(hy));
    __nv_bfloat16 lz = __float2bfloat16(v.z - __bfloat162float(hz));
    __nv_bfloat16 lw = __float2bfloat16(v.w - __bfloat162float(hw));
    __nv_bfloat162 h0(hx, hy), h1(hz, hw), l0(lx, ly), l1(lz, lw);
    h01 = *(uint32_t*)&h0; h23 = *(uint32_t*)&h1;
    l01 = *(uint32_t*)&l0; l23 = *(uint32_t*)&l1;
}

// A: segments [hi, lo, hi]
__global__ void splitA_kernel(const float4* __restrict__ src, int n4) {
    int i = blockIdx.x * blockDim.x + threadIdx.x;
    if (i >= n4) return;
    uint32_t h01, h23, l01, l23;
    split4(src[i], h01, h23, l01, l23);
    size_t row = (size_t)(i >> 7);
    int c = i & 127;                       // float4 index within row (0..127)
    uint2* r = (uint2*)g_A + row * 384;    // 1536 bf16 = 384 uint2 per row
    r[c]       = make_uint2(h01, h23);     // seg0: hi
    r[128 + c] = make_uint2(l01, l23);     // seg1: lo
    r[256 + c] = make_uint2(h01, h23);     // seg2: hi (dup)
}

// B: segments [hi, hi, lo]
__global__ void splitB_kernel(const float4* __restrict__ src, int n4) {
    int i = blockIdx.x * blockDim.x + threadIdx.x;
    if (i >= n4) return;
    uint32_t h01, h23, l01, l23;
    split4(src[i], h01, h23, l01, l23);
    size_t row = (size_t)(i >> 7);
    int c = i & 127;
    uint2* r = (uint2*)g_B + row * 384;
    r[c]       = make_uint2(h01, h23);     // seg0: hi
    r[128 + c] = make_uint2(h01, h23);     // seg1: hi (dup)
    r[256 + c] = make_uint2(l01, l23);     // seg2: lo
}

// ---------------------------------------------------------------------------
// HMMA GEMM: C[m, 512] = (degE[m]*Wdiag[m]) * sum_{k<1536} A[m,k]*B[n,k]
// CTA tile 128x128, 8 warps (64x32 each), mma.sync m16n8k16 bf16 -> f32.
// ---------------------------------------------------------------------------
__device__ __forceinline__ void ldsm4(uint32_t* r, uint32_t a) {
    asm volatile("ldmatrix.sync.aligned.m8n8.x4.shared.b16 {%0,%1,%2,%3}, [%4];"
                 : "=r"(r[0]), "=r"(r[1]), "=r"(r[2]), "=r"(r[3]) : "r"(a));
}
__device__ __forceinline__ void ldsm2(uint32_t* r, uint32_t a) {
    asm volatile("ldmatrix.sync.aligned.m8n8.x2.shared.b16 {%0,%1}, [%2];"
                 : "=r"(r[0]), "=r"(r[1]) : "r"(a));
}
__device__ __forceinline__ void mma16816(float* c, const uint32_t* a, const uint32_t* b) {
    asm volatile("mma.sync.aligned.m16n8k16.row.col.f32.bf16.bf16.f32 "
                 "{%0,%1,%2,%3}, {%4,%5,%6,%7}, {%8,%9}, {%0,%1,%2,%3};"
                 : "+f"(c[0]), "+f"(c[1]), "+f"(c[2]), "+f"(c[3])
                 : "r"(a[0]), "r"(a[1]), "r"(a[2]), "r"(a[3]), "r"(b[0]), "r"(b[1]));
}

__device__ __forceinline__ uint32_t smem_u32(const void* p) {
    uint32_t a;
    asm("{ .reg .u64 t; cvta.to.shared.u64 t, %1; cvt.u32.u64 %0, t; }" : "=r"(a) : "l"(p));
    return a;
}

__global__ __launch_bounds__(256, 2)
void hmma_gemm_kernel(const __nv_bfloat16* __restrict__ A,
                      const __nv_bfloat16* __restrict__ B,
                      const float* __restrict__ degE,
                      const float* __restrict__ Wdiag,
                      float* __restrict__ C, int M) {
    __shared__ __nv_bfloat16 As[128 * ASTR];
    __shared__ __nv_bfloat16 Bs[128 * ASTR];

    int tid  = threadIdx.x;
    int lane = tid & 31;
    int wid  = tid >> 5;
    int bm = blockIdx.y * 128;
    int bn = blockIdx.x * 128;
    int wm = (wid & 1) * 64;      // warp M offset
    int wn = (wid >> 1) * 32;     // warp N offset

    // Global load mapping: 2 threads per row, 16 bf16 (32B) each.
    int lrow = tid >> 1;
    int lc   = (tid & 1) * 16;
    const uint4* Ag = (const uint4*)(A + (size_t)(bm + lrow) * KTOT + lc);
    const uint4* Bg = (const uint4*)(B + (size_t)(bn + lrow) * KTOT + lc);
    uint4* Ast = (uint4*)(As + lrow * ASTR + lc);
    uint4* Bst = (uint4*)(Bs + lrow * ASTR + lc);

    // ldmatrix base addresses (per thread, constant across chunks)
    uint32_t sa = smem_u32(As) + (uint32_t)(((wm + (lane & 15)) * ASTR + (lane >> 4) * 8) * 2);
    uint32_t sb = smem_u32(Bs) + (uint32_t)(((wn + (lane & 7)) * ASTR + ((lane >> 3) & 1) * 8) * 2);

    float acc[4][4][4];
#pragma unroll
    for (int i = 0; i < 4; i++)
#pragma unroll
        for (int j = 0; j < 4; j++)
#pragma unroll
            for (int q = 0; q < 4; q++) acc[i][j][q] = 0.f;

    uint4 pa0 = Ag[0], pa1 = Ag[1];
    uint4 pb0 = Bg[0], pb1 = Bg[1];

    for (int kc = 0; kc < NCH; kc++) {
        Ast[0] = pa0; Ast[1] = pa1;
        Bst[0] = pb0; Bst[1] = pb1;
        __syncthreads();

        if (kc + 1 < NCH) {
            pa0 = Ag[(kc + 1) * 4];  pa1 = Ag[(kc + 1) * 4 + 1];
            pb0 = Bg[(kc + 1) * 4];  pb1 = Bg[(kc + 1) * 4 + 1];
        }

#pragma unroll
        for (int ks = 0; ks < 2; ks++) {
            uint32_t af[4][4], bf[4][2];
#pragma unroll
            for (int mf = 0; mf < 4; mf++)
                ldsm4(af[mf], sa + (uint32_t)(mf * 16 * ASTR * 2 + ks * 32));
#pragma unroll
            for (int nf = 0; nf < 4; nf++)
                ldsm2(bf[nf], sb + (uint32_t)(nf * 8 * ASTR * 2 + ks * 32));
#pragma unroll
            for (int mf = 0; mf < 4; mf++)
#pragma unroll
                for (int nf = 0; nf < 4; nf++)
                    mma16816(acc[mf][nf], af[mf], bf[nf]);
        }
        __syncthreads();
    }

    // Epilogue: fold degE*Wdiag, store fp32.
#pragma unroll
    for (int mf = 0; mf < 4; mf++) {
        int r0 = bm + wm + mf * 16 + (lane >> 2);
        int r1 = r0 + 8;
        float s0 = (r0 < M) ? degE[r0] * Wdiag[r0] : 0.f;
        float s1 = (r1 < M) ? degE[r1] * Wdiag[r1] : 0.f;
#pragma unroll
        for (int nf = 0; nf < 4; nf++) {
            int col = bn + wn + nf * 8 + (lane & 3) * 2;
            if (r0 < M)
                *(float2*)(C + (size_t)r0 * DDIM + col) =
                    make_float2(acc[mf][nf][0] * s0, acc[mf][nf][1] * s0);
            if (r1 < M)
                *(float2*)(C + (size_t)r1 * DDIM + col) =
                    make_float2(acc[mf][nf][2] * s1, acc[mf][nf][3] * s1);
        }
    }
}

// ---------------------------------------------------------------------------
// Stage 2: out[v] += degV[v] * Xep[e]   (edge -> vertex, fp32 reductions)
// ---------------------------------------------------------------------------
__global__ void stage2_kernel(const int* __restrict__ vidx,
                              const int* __restrict__ eidx,
                              const float* __restrict__ degV,
                              float4* __restrict__ out, int nnz) {
    int gid = blockIdx.x * blockDim.x + threadIdx.x;
    int pair = gid >> 7;
    if (pair >= nnz) return;
    int j = gid & 127;
    int v = __ldg(vidx + pair);
    int e = __ldg(eidx + pair);
    float coef = __ldg(degV + v);
    float4 val = ((const float4*)g_Xep)[(size_t)e * D4 + j];
    val.x *= coef; val.y *= coef; val.z *= coef; val.w *= coef;
    float4* dst = out + (size_t)v * D4 + j;
    asm volatile("red.global.add.v4.f32 [%0], {%1,%2,%3,%4};"
                 :: "l"(dst), "f"(val.x), "f"(val.y), "f"(val.z), "f"(val.w) : "memory");
}

// ---------------------------------------------------------------------------
// Launch
// ---------------------------------------------------------------------------
extern "C" void kernel_launch(void* const* d_in, const int* in_sizes, int n_in,
                              void* d_out, int out_size) {
    const float* X     = (const float*)d_in[0];
    const float* W     = (const float*)d_in[1];
    const float* degE  = (const float*)d_in[2];
    const float* degV  = (const float*)d_in[3];
    const float* Wdiag = (const float*)d_in[4];
    const int*   vidx  = (const int*)d_in[5];
    const int*   eidx  = (const int*)d_in[6];
    int nnz = in_sizes[5];
    int E   = in_sizes[2];

    float *Xe, *Xep;
    __nv_bfloat16 *Abuf, *Bbuf;
    cudaGetSymbolAddress((void**)&Xe,   g_Xe);
    cudaGetSymbolAddress((void**)&Xep,  g_Xep);
    cudaGetSymbolAddress((void**)&Abuf, g_A);
    cudaGetSymbolAddress((void**)&Bbuf, g_B);

    // Zero edge accumulators and output (output is poisoned by the harness).
    {
        int n4 = NE * D4;
        zero_kernel<<<(n4 + 255) / 256, 256>>>((float4*)Xe, n4);
    }
    {
        int n4 = out_size / 4;
        zero_kernel<<<(n4 + 255) / 256, 256>>>((float4*)d_out, n4);
    }

    // Split W into [hi|hi|lo] K-concat layout (independent of stage 1).
    {
        int n4 = DDIM * D4;
        splitB_kernel<<<(n4 + 255) / 256, 256>>>((const float4*)W, n4);
    }

    // Stage 1: aggregate raw X into edge accumulators.
    {
        long total = (long)nnz * D4;
        int blocks = (int)((total + 255) / 256);
        stage1_kernel<<<blocks, 256>>>((const float4*)X, vidx, eidx, nnz);
    }

    // Split Xe into [hi|lo|hi] K-concat layout.
    {
        int n4 = NE * D4;
        splitA_kernel<<<(n4 + 255) / 256, 256>>>((const float4*)Xe, n4);
    }

    // Tensor-core projection: Xep = (degE*Wdiag) ⊙ (Xe @ W^T), K=1536 concat.
    {
        dim3 grid(DDIM / 128, NE_PAD / 128);   // x: N-block (A reuse in L2), y: M-block
        hmma_gemm_kernel<<<grid, 256>>>(Abuf, Bbuf, degE, Wdiag, Xep, E);
    }

    // Stage 2: edge -> vertex with degV.
    {
        long total = (long)nnz * D4;
        int blocks = (int)((total + 255) / 256);
        stage2_kernel<<<blocks, 256>>>(vidx, eidx, degV, (float4*)d_out, nnz);
    }
}

// round 10
// speedup vs baseline: 2.5067x; 1.4658x over previous
#include <cuda_runtime.h>
#include <cuda_bf16.h>
#include <cstdint>

// Problem constants (fixed by dataset)
#define NV     50000
#define NE     25000
#define NE_PAD 25088          // 196 * 128
#define DDIM   512
#define D4     128            // DDIM/4
#define KTOT   1536           // 3 * DDIM (K-concat of bf16 splits)
#define NCH    48             // KTOT / 32
#define ASTR   40             // smem row stride in bf16 (conflict-free ldmatrix)

// ---------------------------------------------------------------------------
// Scratch (__device__ globals; pad rows of g_A stay zero from static init)
// ---------------------------------------------------------------------------
__device__ float          g_Xep[(size_t)NE * DDIM];        // projected edges [E, D]
__device__ __nv_bfloat16  g_A  [(size_t)NE_PAD * KTOT];    // [hi(Xe) | lo(Xe) | hi(Xe)]
__device__ __nv_bfloat16  g_B  [(size_t)DDIM * KTOT];      // [hi(W)  | hi(W)  | lo(W) ]
// CSR scratch
__device__ int g_cntE[NE],     g_cntV[NV];
__device__ int g_offE[NE + 1], g_offV[NV + 1];
__device__ int g_curE[NE],     g_curV[NV];
__device__ int g_adjE[400000 + 64];   // per-edge vertex lists
__device__ int g_adjV[400000 + 64];   // per-vertex edge lists

// ---------------------------------------------------------------------------
// CSR build: zero counters -> histogram -> scan -> fill
// ---------------------------------------------------------------------------
__global__ void zero_counts_kernel() {
    int i = blockIdx.x * blockDim.x + threadIdx.x;
    if (i < NE) g_cntE[i] = 0;
    if (i < NV) g_cntV[i] = 0;
}

__global__ void hist_kernel(const int* __restrict__ vidx,
                            const int* __restrict__ eidx, int nnz) {
    int i = blockIdx.x * blockDim.x + threadIdx.x;
    if (i >= nnz) return;
    atomicAdd(&g_cntE[__ldg(eidx + i)], 1);
    atomicAdd(&g_cntV[__ldg(vidx + i)], 1);
}

// Single-block exclusive scan (n up to ~64k): counts -> offs[0..n], cursor
__global__ __launch_bounds__(1024)
void scan_kernel(const int* __restrict__ counts, int* __restrict__ offs,
                 int* __restrict__ cursor, int n) {
    __shared__ int part[1024];
    int tid = threadIdx.x;
    int tpc = (n + 1023) >> 10;
    int base = tid * tpc;
    int sum = 0;
    for (int i = 0; i < tpc; i++)
        if (base + i < n) sum += counts[base + i];
    part[tid] = sum;
    __syncthreads();
#pragma unroll
    for (int d = 1; d < 1024; d <<= 1) {
        int t = (tid >= d) ? part[tid - d] : 0;
        __syncthreads();
        part[tid] += t;
        __syncthreads();
    }
    int run = tid ? part[tid - 1] : 0;
    for (int i = 0; i < tpc; i++) {
        if (base + i < n) {
            offs[base + i] = run;
            cursor[base + i] = run;
            run += counts[base + i];
        }
    }
    if (tid == 0) offs[n] = part[1023];
}

__global__ void fill_kernel(const int* __restrict__ vidx,
                            const int* __restrict__ eidx, int nnz) {
    int i = blockIdx.x * blockDim.x + threadIdx.x;
    if (i >= nnz) return;
    int v = __ldg(vidx + i);
    int e = __ldg(eidx + i);
    int pe = atomicAdd(&g_curE[e], 1);
    g_adjE[pe] = v;
    int pv = atomicAdd(&g_curV[v], 1);
    g_adjV[pv] = e;
}

// ---------------------------------------------------------------------------
// bf16 hi/lo split helper
// ---------------------------------------------------------------------------
__device__ __forceinline__ void split4(float4 v, uint32_t& h01, uint32_t& h23,
                                       uint32_t& l01, uint32_t& l23) {
    __nv_bfloat16 hx = __float2bfloat16(v.x), hy = __float2bfloat16(v.y);
    __nv_bfloat16 hz = __float2bfloat16(v.z), hw = __float2bfloat16(v.w);
    __nv_bfloat16 lx = __float2bfloat16(v.x - __bfloat162float(hx));
    __nv_bfloat16 ly = __float2bfloat16(v.y - __bfloat162float(hy));
    __nv_bfloat16 lz = __float2bfloat16(v.z - __bfloat162float(hz));
    __nv_bfloat16 lw = __float2bfloat16(v.w - __bfloat162float(hw));
    __nv_bfloat162 h0(hx, hy), h1(hz, hw), l0(lx, ly), l1(lz, lw);
    h01 = *(uint32_t*)&h0; h23 = *(uint32_t*)&h1;
    l01 = *(uint32_t*)&l0; l23 = *(uint32_t*)&l1;
}

// ---------------------------------------------------------------------------
// Stage 1 (gather): per-edge block sums gathered X rows, writes bf16 split
// directly into the GEMM A-buffer ([hi | lo | hi] K-concat).
// ---------------------------------------------------------------------------
__global__ __launch_bounds__(128)
void stage1_gather(const float4* __restrict__ X) {
    int e = blockIdx.x;
    int j = threadIdx.x;                 // 0..127, one float4 column group
    int s = g_offE[e], t = g_offE[e + 1];
    float4 acc = make_float4(0.f, 0.f, 0.f, 0.f);
    for (int k = s; k < t; k++) {
        int v = __ldg(g_adjE + k);       // broadcast across block
        float4 x = X[(size_t)v * D4 + j];
        acc.x += x.x; acc.y += x.y; acc.z += x.z; acc.w += x.w;
    }
    uint32_t h01, h23, l01, l23;
    split4(acc, h01, h23, l01, l23);
    uint2* r = (uint2*)g_A + (size_t)e * 384;    // 1536 bf16 = 384 uint2
    r[j]       = make_uint2(h01, h23);   // seg0: hi
    r[128 + j] = make_uint2(l01, l23);   // seg1: lo
    r[256 + j] = make_uint2(h01, h23);   // seg2: hi (dup)
}

// B: segments [hi, hi, lo]
__global__ void splitB_kernel(const float4* __restrict__ src, int n4) {
    int i = blockIdx.x * blockDim.x + threadIdx.x;
    if (i >= n4) return;
    uint32_t h01, h23, l01, l23;
    split4(src[i], h01, h23, l01, l23);
    size_t row = (size_t)(i >> 7);
    int c = i & 127;
    uint2* r = (uint2*)g_B + row * 384;
    r[c]       = make_uint2(h01, h23);
    r[128 + c] = make_uint2(h01, h23);
    r[256 + c] = make_uint2(l01, l23);
}

// ---------------------------------------------------------------------------
// HMMA GEMM: C[m, 512] = (degE[m]*Wdiag[m]) * sum_{k<1536} A[m,k]*B[n,k]
// CTA tile 128x128, 8 warps (64x32 each), mma.sync m16n8k16 bf16 -> f32.
// ---------------------------------------------------------------------------
__device__ __forceinline__ void ldsm4(uint32_t* r, uint32_t a) {
    asm volatile("ldmatrix.sync.aligned.m8n8.x4.shared.b16 {%0,%1,%2,%3}, [%4];"
                 : "=r"(r[0]), "=r"(r[1]), "=r"(r[2]), "=r"(r[3]) : "r"(a));
}
__device__ __forceinline__ void ldsm2(uint32_t* r, uint32_t a) {
    asm volatile("ldmatrix.sync.aligned.m8n8.x2.shared.b16 {%0,%1}, [%2];"
                 : "=r"(r[0]), "=r"(r[1]) : "r"(a));
}
__device__ __forceinline__ void mma16816(float* c, const uint32_t* a, const uint32_t* b) {
    asm volatile("mma.sync.aligned.m16n8k16.row.col.f32.bf16.bf16.f32 "
                 "{%0,%1,%2,%3}, {%4,%5,%6,%7}, {%8,%9}, {%0,%1,%2,%3};"
                 : "+f"(c[0]), "+f"(c[1]), "+f"(c[2]), "+f"(c[3])
                 : "r"(a[0]), "r"(a[1]), "r"(a[2]), "r"(a[3]), "r"(b[0]), "r"(b[1]));
}
__device__ __forceinline__ uint32_t smem_u32(const void* p) {
    uint32_t a;
    asm("{ .reg .u64 t; cvta.to.shared.u64 t, %1; cvt.u32.u64 %0, t; }" : "=r"(a) : "l"(p));
    return a;
}

__global__ __launch_bounds__(256, 2)
void hmma_gemm_kernel(const __nv_bfloat16* __restrict__ A,
                      const __nv_bfloat16* __restrict__ B,
                      const float* __restrict__ degE,
                      const float* __restrict__ Wdiag,
                      float* __restrict__ C, int M) {
    __shared__ __nv_bfloat16 As[128 * ASTR];
    __shared__ __nv_bfloat16 Bs[128 * ASTR];

    int tid  = threadIdx.x;
    int lane = tid & 31;
    int wid  = tid >> 5;
    int bm = blockIdx.y * 128;
    int bn = blockIdx.x * 128;
    int wm = (wid & 1) * 64;
    int wn = (wid >> 1) * 32;

    int lrow = tid >> 1;
    int lc   = (tid & 1) * 16;
    const uint4* Ag = (const uint4*)(A + (size_t)(bm + lrow) * KTOT + lc);
    const uint4* Bg = (const uint4*)(B + (size_t)(bn + lrow) * KTOT + lc);
    uint4* Ast = (uint4*)(As + lrow * ASTR + lc);
    uint4* Bst = (uint4*)(Bs + lrow * ASTR + lc);

    uint32_t sa = smem_u32(As) + (uint32_t)(((wm + (lane & 15)) * ASTR + (lane >> 4) * 8) * 2);
    uint32_t sb = smem_u32(Bs) + (uint32_t)(((wn + (lane & 7)) * ASTR + ((lane >> 3) & 1) * 8) * 2);

    float acc[4][4][4];
#pragma unroll
    for (int i = 0; i < 4; i++)
#pragma unroll
        for (int j = 0; j < 4; j++)
#pragma unroll
            for (int q = 0; q < 4; q++) acc[i][j][q] = 0.f;

    uint4 pa0 = Ag[0], pa1 = Ag[1];
    uint4 pb0 = Bg[0], pb1 = Bg[1];

    for (int kc = 0; kc < NCH; kc++) {
        Ast[0] = pa0; Ast[1] = pa1;
        Bst[0] = pb0; Bst[1] = pb1;
        __syncthreads();

        if (kc + 1 < NCH) {
            pa0 = Ag[(kc + 1) * 4];  pa1 = Ag[(kc + 1) * 4 + 1];
            pb0 = Bg[(kc + 1) * 4];  pb1 = Bg[(kc + 1) * 4 + 1];
        }

#pragma unroll
        for (int ks = 0; ks < 2; ks++) {
            uint32_t af[4][4], bf[4][2];
#pragma unroll
            for (int mf = 0; mf < 4; mf++)
                ldsm4(af[mf], sa + (uint32_t)(mf * 16 * ASTR * 2 + ks * 32));
#pragma unroll
            for (int nf = 0; nf < 4; nf++)
                ldsm2(bf[nf], sb + (uint32_t)(nf * 8 * ASTR * 2 + ks * 32));
#pragma unroll
            for (int mf = 0; mf < 4; mf++)
#pragma unroll
                for (int nf = 0; nf < 4; nf++)
                    mma16816(acc[mf][nf], af[mf], bf[nf]);
        }
        __syncthreads();
    }

#pragma unroll
    for (int mf = 0; mf < 4; mf++) {
        int r0 = bm + wm + mf * 16 + (lane >> 2);
        int r1 = r0 + 8;
        float s0 = (r0 < M) ? degE[r0] * Wdiag[r0] : 0.f;
        float s1 = (r1 < M) ? degE[r1] * Wdiag[r1] : 0.f;
#pragma unroll
        for (int nf = 0; nf < 4; nf++) {
            int col = bn + wn + nf * 8 + (lane & 3) * 2;
            if (r0 < M)
                *(float2*)(C + (size_t)r0 * DDIM + col) =
                    make_float2(acc[mf][nf][0] * s0, acc[mf][nf][1] * s0);
            if (r1 < M)
                *(float2*)(C + (size_t)r1 * DDIM + col) =
                    make_float2(acc[mf][nf][2] * s1, acc[mf][nf][3] * s1);
        }
    }
}

// ---------------------------------------------------------------------------
// Stage 2 (gather): per-vertex block sums gathered Xep rows, scales by degV,
// writes each output row exactly once (no atomics, no pre-zero).
// ---------------------------------------------------------------------------
__global__ __launch_bounds__(128)
void stage2_gather(const float* __restrict__ degV, float4* __restrict__ out) {
    int v = blockIdx.x;
    int j = threadIdx.x;
    int s = g_offV[v], t = g_offV[v + 1];
    float4 acc = make_float4(0.f, 0.f, 0.f, 0.f);
    for (int k = s; k < t; k++) {
        int e = __ldg(g_adjV + k);
        float4 p = ((const float4*)g_Xep)[(size_t)e * D4 + j];
        acc.x += p.x; acc.y += p.y; acc.z += p.z; acc.w += p.w;
    }
    float c = __ldg(degV + v);
    acc.x *= c; acc.y *= c; acc.z *= c; acc.w *= c;
    out[(size_t)v * D4 + j] = acc;
}

// ---------------------------------------------------------------------------
// Launch
// ---------------------------------------------------------------------------
extern "C" void kernel_launch(void* const* d_in, const int* in_sizes, int n_in,
                              void* d_out, int out_size) {
    const float* X     = (const float*)d_in[0];
    const float* W     = (const float*)d_in[1];
    const float* degE  = (const float*)d_in[2];
    const float* degV  = (const float*)d_in[3];
    const float* Wdiag = (const float*)d_in[4];
    const int*   vidx  = (const int*)d_in[5];
    const int*   eidx  = (const int*)d_in[6];
    int nnz = in_sizes[5];
    int E   = in_sizes[2];

    float* Xep;
    __nv_bfloat16 *Abuf, *Bbuf;
    int *cntE, *cntV, *offE, *offV, *curE, *curV;
    cudaGetSymbolAddress((void**)&Xep,  g_Xep);
    cudaGetSymbolAddress((void**)&Abuf, g_A);
    cudaGetSymbolAddress((void**)&Bbuf, g_B);
    cudaGetSymbolAddress((void**)&cntE, g_cntE);
    cudaGetSymbolAddress((void**)&cntV, g_cntV);
    cudaGetSymbolAddress((void**)&offE, g_offE);
    cudaGetSymbolAddress((void**)&offV, g_offV);
    cudaGetSymbolAddress((void**)&curE, g_curE);
    cudaGetSymbolAddress((void**)&curV, g_curV);

    // CSR build
    zero_counts_kernel<<<(NV + 255) / 256, 256>>>();
    hist_kernel<<<(nnz + 255) / 256, 256>>>(vidx, eidx, nnz);
    scan_kernel<<<1, 1024>>>(cntE, offE, curE, NE);
    scan_kernel<<<1, 1024>>>(cntV, offV, curV, NV);
    fill_kernel<<<(nnz + 255) / 256, 256>>>(vidx, eidx, nnz);

    // Split W into [hi|hi|lo] K-concat layout (independent of CSR).
    splitB_kernel<<<(DDIM * D4 + 255) / 256, 256>>>((const float4*)W, DDIM * D4);

    // Stage 1: per-edge gather-sum of X, fused bf16 split into A buffer.
    stage1_gather<<<NE, 128>>>((const float4*)X);

    // Tensor-core projection: Xep = (degE*Wdiag) ⊙ (Xe @ W^T), K=1536 concat.
    {
        dim3 grid(DDIM / 128, NE_PAD / 128);
        hmma_gemm_kernel<<<grid, 256>>>(Abuf, Bbuf, degE, Wdiag, Xep, E);
    }

    // Stage 2: per-vertex gather-sum of Xep, scaled by degV, direct store.
    stage2_gather<<<NV, 128>>>(degV, (float4*)d_out);
}